// round 2
// baseline (speedup 1.0000x reference)
#include <cuda_runtime.h>
#include <cuda_bf16.h>
#include <math.h>

// Problem constants
#define B 4
#define T 512
#define C 256
#define C2 512
#define HEADS 4
#define MAXOFF 2

// Scratch for subj/obj projections (allocation-free: device globals)
__device__ float g_subj[B * T * C];
__device__ float g_obj[B * T * C];

// ---------------------------------------------------------------------------
// Kernel 1: max-pool along channel (window 5, pad 2) + concat -> x_new
// ---------------------------------------------------------------------------
__global__ void pool_concat_kernel(const float* __restrict__ x,
                                   float* __restrict__ xnew) {
    int idx = blockIdx.x * 256 + threadIdx.x;
    if (idx >= B * T * C2) return;
    int cc = idx & (C2 - 1);
    int bt = idx >> 9;
    const float* xr = x + bt * C;
    float v;
    if (cc < C) {
        int lo = cc - MAXOFF; if (lo < 0) lo = 0;
        int hi = cc + MAXOFF; if (hi > C - 1) hi = C - 1;
        v = -INFINITY;
        #pragma unroll 5
        for (int c = lo; c <= hi; c++) v = fmaxf(v, xr[c]);
    } else {
        v = xr[cc - C];
    }
    xnew[idx] = v;
}

// ---------------------------------------------------------------------------
// Kernel 2: GEMM  out[M,N] = A[M,K] @ W[K,N] + bias[N]
// M=2048, N=256, K=512.  64x64 tile, BK=16, 4x4 microtile, 256 threads.
// ---------------------------------------------------------------------------
__global__ void gemm_kernel(const float* __restrict__ A,
                            const float* __restrict__ W,
                            const float* __restrict__ bias,
                            float* __restrict__ out) {
    const int N = C;          // 256
    const int K = C2;         // 512

    __shared__ float As[16][68];   // [k][m], padded
    __shared__ float Ws[16][64];   // [k][n]

    int tid = threadIdx.x;
    int tx = tid & 15;   // n direction
    int ty = tid >> 4;   // m direction
    int bm = blockIdx.y * 64;
    int bn = blockIdx.x * 64;

    float acc[4][4];
    #pragma unroll
    for (int i = 0; i < 4; i++)
        #pragma unroll
        for (int j = 0; j < 4; j++) acc[i][j] = 0.0f;

    for (int k0 = 0; k0 < K; k0 += 16) {
        #pragma unroll
        for (int l = 0; l < 4; l++) {
            int idx = tid + l * 256;
            int m = idx >> 4, ka = idx & 15;
            As[ka][m] = A[(bm + m) * K + k0 + ka];
            int n2 = idx & 63, kw = idx >> 6;
            Ws[kw][n2] = W[(k0 + kw) * N + bn + n2];
        }
        __syncthreads();
        #pragma unroll
        for (int k = 0; k < 16; k++) {
            float a[4], w[4];
            #pragma unroll
            for (int i = 0; i < 4; i++) a[i] = As[k][ty * 4 + i];
            float4 wv = *(const float4*)&Ws[k][tx * 4];
            w[0] = wv.x; w[1] = wv.y; w[2] = wv.z; w[3] = wv.w;
            #pragma unroll
            for (int i = 0; i < 4; i++)
                #pragma unroll
                for (int j = 0; j < 4; j++)
                    acc[i][j] += a[i] * w[j];
        }
        __syncthreads();
    }

    float4 bv = *(const float4*)&bias[bn + tx * 4];
    #pragma unroll
    for (int i = 0; i < 4; i++) {
        float4 o;
        o.x = acc[i][0] + bv.x;
        o.y = acc[i][1] + bv.y;
        o.z = acc[i][2] + bv.z;
        o.w = acc[i][3] + bv.w;
        *(float4*)&out[(bm + ty * 4 + i) * N + bn + tx * 4] = o;
    }
}

// ---------------------------------------------------------------------------
// Kernel 3: rep + relu + softmax(axis=j) + mask  ->  attn (B,T,T,HEADS)
// Grid: B * (T/16) = 128 blocks; 256 threads = 16 ii x 16 jj.
// ---------------------------------------------------------------------------
__global__ void rep_softmax_kernel(const float* __restrict__ subj,
                                   const float* __restrict__ obj,
                                   const float* __restrict__ W_t,
                                   const float* __restrict__ b_t,
                                   const int* __restrict__ mask,
                                   float* __restrict__ attn) {
    __shared__ float w_sh[C * HEADS];          // [c*4+h], 4KB
    __shared__ float obj_sh[C * 17];           // [c][ii], stride 17
    __shared__ float subj_sh[C * 17];          // [c][jj], stride 17
    __shared__ float red[16 * 16 * 4];         // reduction scratch

    int tid = threadIdx.x;
    int jj = tid & 15;
    int ii = tid >> 4;
    int b = blockIdx.x >> 5;
    int i_base = (blockIdx.x & 31) << 4;
    int i = i_base + ii;

    for (int idx = tid; idx < C * HEADS; idx += 256) w_sh[idx] = W_t[idx];
    float bt0 = b_t[0], bt1 = b_t[1], bt2 = b_t[2], bt3 = b_t[3];

    #pragma unroll
    for (int l = 0; l < 16; l++) {
        int idx = tid + l * 256;
        int row = idx >> 8, c = idx & 255;
        obj_sh[c * 17 + row] = obj[(b * T + i_base + row) * C + c];
    }
    __syncthreads();

    float mloc0 = 0.f, mloc1 = 0.f, mloc2 = 0.f, mloc3 = 0.f; // z >= 0 always
    const float4* wv = (const float4*)w_sh;
    size_t attn_base = ((size_t)(b * T + i)) * T * HEADS;

    // ---- Pass 1: z = relu(rep), write to gmem, track per-thread max ----
    for (int jb = 0; jb < T / 16; jb++) {
        #pragma unroll
        for (int l = 0; l < 16; l++) {
            int idx = tid + l * 256;
            int row = idx >> 8, c = idx & 255;
            subj_sh[c * 17 + row] = subj[(b * T + jb * 16 + row) * C + c];
        }
        __syncthreads();

        float a0 = 0.f, a1 = 0.f, a2 = 0.f, a3 = 0.f;
        #pragma unroll 8
        for (int c = 0; c < C; c++) {
            float s = subj_sh[c * 17 + jj];
            float o = obj_sh[c * 17 + ii];
            float ad = fabsf(s - o);
            float4 w = wv[c];
            a0 += ad * w.x;
            a1 += ad * w.y;
            a2 += ad * w.z;
            a3 += ad * w.w;
        }
        float4 z;
        z.x = fmaxf(a0 + bt0, 0.f);
        z.y = fmaxf(a1 + bt1, 0.f);
        z.z = fmaxf(a2 + bt2, 0.f);
        z.w = fmaxf(a3 + bt3, 0.f);
        mloc0 = fmaxf(mloc0, z.x);
        mloc1 = fmaxf(mloc1, z.y);
        mloc2 = fmaxf(mloc2, z.z);
        mloc3 = fmaxf(mloc3, z.w);
        int j = jb * 16 + jj;
        *(float4*)&attn[attn_base + (size_t)j * HEADS] = z;
        __syncthreads();
    }

    // ---- reduce max across jj for each (ii, h) ----
    float4* red4 = (float4*)red;
    red4[ii * 16 + jj] = make_float4(mloc0, mloc1, mloc2, mloc3);
    __syncthreads();
    float mx0 = 0.f, mx1 = 0.f, mx2 = 0.f, mx3 = 0.f;
    #pragma unroll
    for (int p = 0; p < 16; p++) {
        float4 v = red4[ii * 16 + p];
        mx0 = fmaxf(mx0, v.x);
        mx1 = fmaxf(mx1, v.y);
        mx2 = fmaxf(mx2, v.z);
        mx3 = fmaxf(mx3, v.w);
    }
    __syncthreads();

    // ---- Pass 2: sum of exp(z - max) over j ----
    float s0 = 0.f, s1 = 0.f, s2 = 0.f, s3 = 0.f;
    for (int jb = 0; jb < T / 16; jb++) {
        int j = jb * 16 + jj;
        float4 z = *(const float4*)&attn[attn_base + (size_t)j * HEADS];
        s0 += expf(z.x - mx0);
        s1 += expf(z.y - mx1);
        s2 += expf(z.z - mx2);
        s3 += expf(z.w - mx3);
    }
    red4[ii * 16 + jj] = make_float4(s0, s1, s2, s3);
    __syncthreads();
    float t0 = 0.f, t1 = 0.f, t2 = 0.f, t3 = 0.f;
    #pragma unroll
    for (int p = 0; p < 16; p++) {
        float4 v = red4[ii * 16 + p];
        t0 += v.x; t1 += v.y; t2 += v.z; t3 += v.w;
    }
    float r0 = 1.0f / t0, r1 = 1.0f / t1, r2 = 1.0f / t2, r3 = 1.0f / t3;

    // ---- Pass 3: normalize + mask ----
    int mi = mask[b * T + i];
    for (int jb = 0; jb < T / 16; jb++) {
        int j = jb * 16 + jj;
        float4 z = *(const float4*)&attn[attn_base + (size_t)j * HEADS];
        int mj = mask[b * T + j];
        float kill = (mi && mj) ? 0.0f : 1.0f;
        float4 o;
        o.x = expf(z.x - mx0) * r0 * kill;
        o.y = expf(z.y - mx1) * r1 * kill;
        o.z = expf(z.z - mx2) * r2 * kill;
        o.w = expf(z.w - mx3) * r3 * kill;
        *(float4*)&attn[attn_base + (size_t)j * HEADS] = o;
    }
}

// ---------------------------------------------------------------------------
extern "C" void kernel_launch(void* const* d_in, const int* in_sizes, int n_in,
                              void* d_out, int out_size) {
    const float* x      = (const float*)d_in[0];
    const float* W_subj = (const float*)d_in[1];
    const float* b_subj = (const float*)d_in[2];
    const float* W_obj  = (const float*)d_in[3];
    const float* b_obj  = (const float*)d_in[4];
    const float* W_t    = (const float*)d_in[5];
    const float* b_t    = (const float*)d_in[6];
    const int*   mask   = (const int*)d_in[7];

    float* out   = (float*)d_out;
    float* xnew  = out;                          // (B,T,2C)
    float* attn  = out + (size_t)B * T * C2;     // (B,T,T,HEADS)

    float* subj;
    float* obj;
    cudaGetSymbolAddress((void**)&subj, g_subj);
    cudaGetSymbolAddress((void**)&obj, g_obj);

    pool_concat_kernel<<<(B * T * C2 + 255) / 256, 256>>>(x, xnew);

    dim3 gg(C / 64, (B * T) / 64);   // (4, 32)
    gemm_kernel<<<gg, 256>>>(xnew, W_subj, b_subj, subj);
    gemm_kernel<<<gg, 256>>>(xnew, W_obj, b_obj, obj);

    rep_softmax_kernel<<<B * (T / 16), 256>>>(subj, obj, W_t, b_t, mask, attn);
}

// round 3
// speedup vs baseline: 1.9744x; 1.9744x over previous
#include <cuda_runtime.h>
#include <cuda_bf16.h>
#include <math.h>

// Problem constants
#define B 4
#define T 512
#define C 256
#define C2 512
#define HEADS 4
#define MAXOFF 2

#define TI 32          // i-tile per block
#define TJ 32          // j-tile per block
#define NJT (T / TJ)   // 16 j-tiles
#define CK 128         // c chunk

typedef unsigned long long u64;

// Scratch (allocation-free: device globals)
__device__ float g_subj[B * T * C];
__device__ float g_obj[B * T * C];
__device__ float g_part[B * T * NJT * HEADS];   // partial exp-sums per j-tile

// packed f32x2 helpers
static __device__ __forceinline__ u64 add2(u64 a, u64 b) {
    u64 r; asm("add.rn.f32x2 %0, %1, %2;" : "=l"(r) : "l"(a), "l"(b)); return r;
}
static __device__ __forceinline__ u64 fma2(u64 a, u64 b, u64 c) {
    u64 r; asm("fma.rn.f32x2 %0, %1, %2, %3;" : "=l"(r) : "l"(a), "l"(b), "l"(c)); return r;
}
static __device__ __forceinline__ float2 unpack2(u64 v) {
    float2 r; asm("mov.b64 {%0, %1}, %2;" : "=f"(r.x), "=f"(r.y) : "l"(v)); return r;
}
#define FABS2(v) ((v) & 0x7fffffff7fffffffULL)

// ---------------------------------------------------------------------------
// Kernel 1: max-pool along channel (window 5, pad 2) + concat -> x_new
// ---------------------------------------------------------------------------
__global__ void pool_concat_kernel(const float* __restrict__ x,
                                   float* __restrict__ xnew) {
    int idx = blockIdx.x * 256 + threadIdx.x;
    if (idx >= B * T * C2) return;
    int cc = idx & (C2 - 1);
    int bt = idx >> 9;
    const float* xr = x + bt * C;
    float v;
    if (cc < C) {
        int lo = cc - MAXOFF; if (lo < 0) lo = 0;
        int hi = cc + MAXOFF; if (hi > C - 1) hi = C - 1;
        v = -INFINITY;
        #pragma unroll 5
        for (int c = lo; c <= hi; c++) v = fmaxf(v, xr[c]);
    } else {
        v = xr[cc - C];
    }
    xnew[idx] = v;
}

// ---------------------------------------------------------------------------
// Kernel 2: both projection GEMMs in one launch (blockIdx.z selects W/bias/out)
// out[M,N] = A[M,K] @ W[K,N] + bias[N];  M=2048, N=256, K=512.
// ---------------------------------------------------------------------------
__global__ void gemm_kernel(const float* __restrict__ A,
                            const float* __restrict__ W0,
                            const float* __restrict__ b0,
                            const float* __restrict__ W1,
                            const float* __restrict__ b1,
                            float* __restrict__ out0,
                            float* __restrict__ out1) {
    const int N = C;
    const int K = C2;

    const float* W    = blockIdx.z ? W1 : W0;
    const float* bias = blockIdx.z ? b1 : b0;
    float* out        = blockIdx.z ? out1 : out0;

    __shared__ float As[16][68];
    __shared__ float Ws[16][64];

    int tid = threadIdx.x;
    int tx = tid & 15;
    int ty = tid >> 4;
    int bm = blockIdx.y * 64;
    int bn = blockIdx.x * 64;

    float acc[4][4];
    #pragma unroll
    for (int i = 0; i < 4; i++)
        #pragma unroll
        for (int j = 0; j < 4; j++) acc[i][j] = 0.0f;

    for (int k0 = 0; k0 < K; k0 += 16) {
        #pragma unroll
        for (int l = 0; l < 4; l++) {
            int idx = tid + l * 256;
            int m = idx >> 4, ka = idx & 15;
            As[ka][m] = A[(bm + m) * K + k0 + ka];
            int n2 = idx & 63, kw = idx >> 6;
            Ws[kw][n2] = W[(k0 + kw) * N + bn + n2];
        }
        __syncthreads();
        #pragma unroll
        for (int k = 0; k < 16; k++) {
            float a[4], w[4];
            #pragma unroll
            for (int i = 0; i < 4; i++) a[i] = As[k][ty * 4 + i];
            float4 wv = *(const float4*)&Ws[k][tx * 4];
            w[0] = wv.x; w[1] = wv.y; w[2] = wv.z; w[3] = wv.w;
            #pragma unroll
            for (int i = 0; i < 4; i++)
                #pragma unroll
                for (int j = 0; j < 4; j++)
                    acc[i][j] += a[i] * w[j];
        }
        __syncthreads();
    }

    float4 bv = *(const float4*)&bias[bn + tx * 4];
    #pragma unroll
    for (int i = 0; i < 4; i++) {
        float4 o;
        o.x = acc[i][0] + bv.x;
        o.y = acc[i][1] + bv.y;
        o.z = acc[i][2] + bv.z;
        o.w = acc[i][3] + bv.w;
        *(float4*)&out[(bm + ty * 4 + i) * N + bn + tx * 4] = o;
    }
}

// ---------------------------------------------------------------------------
// Kernel 3a: e = exp(relu(rep)) for a 32x32 (i,j) tile; write e to attn and
// per-(i,h) partial sums (over this tile's 32 j) to g_part.
// Grid (NJT, T/TI, B), 256 threads = 16(ty->i pairs) x 16(tx->j pairs).
// Microtile 2i x 2j per thread; c packed in f32x2 pairs.
// ---------------------------------------------------------------------------
__global__ void __launch_bounds__(256)
rep_exp_kernel(const float* __restrict__ subj,
               const float* __restrict__ obj,
               const float* __restrict__ W_t,
               const float* __restrict__ b_t,
               float* __restrict__ attn,
               float* __restrict__ part) {
    __shared__ float s_sh[TJ * CK];     // [jrow][c], swizzled
    __shared__ float o_sh[TI * CK];     // [irow][c], swizzled, holds -obj
    __shared__ float w_sh[HEADS * C];   // [h][c]

    const int tid = threadIdx.x;
    const int tx = tid & 15;
    const int ty = tid >> 4;
    const int jt = blockIdx.x;
    const int j0 = jt * TJ;
    const int i0 = blockIdx.y * TI;
    const int b  = blockIdx.z;

    // Load W_t transposed: w_sh[h][c] = W_t[c*4+h]
    {
        float4 wv = *(const float4*)&W_t[tid * 4];
        w_sh[0 * C + tid] = wv.x;
        w_sh[1 * C + tid] = wv.y;
        w_sh[2 * C + tid] = wv.z;
        w_sh[3 * C + tid] = wv.w;
    }

    u64 acc[2][2][4];
    #pragma unroll
    for (int p = 0; p < 2; p++)
        #pragma unroll
        for (int q = 0; q < 2; q++)
            #pragma unroll
            for (int h = 0; h < 4; h++) acc[p][q][h] = 0ULL;

    const int swj = tx & 7;
    const int swi = ty & 7;
    const float* sp0 = s_sh + (2 * tx) * CK;
    const float* sp1 = sp0 + CK;
    const float* op0 = o_sh + (2 * ty) * CK;
    const float* op1 = op0 + CK;

    for (int ck = 0; ck < C / CK; ck++) {
        const int cbase = ck * CK;
        // load s/o chunk (32 rows x 128 c), coalesced gmem, swizzled smem
        #pragma unroll
        for (int l = 0; l < 4; l++) {
            int t = tid + l * 256;
            int row = t >> 5;          // 0..31
            int ccg = t & 31;          // 16B group within chunk
            int phys = (ccg ^ ((row >> 1) & 7)) << 2;
            float4 sv = *(const float4*)&subj[(b * T + j0 + row) * C + cbase + ccg * 4];
            *(float4*)&s_sh[row * CK + phys] = sv;
            float4 ov = *(const float4*)&obj[(b * T + i0 + row) * C + cbase + ccg * 4];
            ov.x = -ov.x; ov.y = -ov.y; ov.z = -ov.z; ov.w = -ov.w;
            *(float4*)&o_sh[row * CK + phys] = ov;
        }
        __syncthreads();

        const float* wp0 = w_sh + 0 * C + cbase;
        const float* wp1 = w_sh + 1 * C + cbase;
        const float* wp2 = w_sh + 2 * C + cbase;
        const float* wp3 = w_sh + 3 * C + cbase;

        #pragma unroll 4
        for (int cc4 = 0; cc4 < CK; cc4 += 4) {
            int g = cc4 >> 2;
            ulonglong2 S0 = *(const ulonglong2*)(sp0 + ((g ^ swj) << 2));
            ulonglong2 S1 = *(const ulonglong2*)(sp1 + ((g ^ swj) << 2));
            ulonglong2 P0 = *(const ulonglong2*)(op0 + ((g ^ swi) << 2));
            ulonglong2 P1 = *(const ulonglong2*)(op1 + ((g ^ swi) << 2));
            ulonglong2 W0 = *(const ulonglong2*)(wp0 + cc4);
            ulonglong2 W1 = *(const ulonglong2*)(wp1 + cc4);
            ulonglong2 W2 = *(const ulonglong2*)(wp2 + cc4);
            ulonglong2 W3 = *(const ulonglong2*)(wp3 + cc4);

            // c-pair (c, c+1)
            {
                u64 a00 = FABS2(add2(S0.x, P0.x));   // p=0,q=0
                u64 a01 = FABS2(add2(S1.x, P0.x));   // p=0,q=1
                u64 a10 = FABS2(add2(S0.x, P1.x));   // p=1,q=0
                u64 a11 = FABS2(add2(S1.x, P1.x));   // p=1,q=1
                acc[0][0][0] = fma2(a00, W0.x, acc[0][0][0]);
                acc[0][0][1] = fma2(a00, W1.x, acc[0][0][1]);
                acc[0][0][2] = fma2(a00, W2.x, acc[0][0][2]);
                acc[0][0][3] = fma2(a00, W3.x, acc[0][0][3]);
                acc[0][1][0] = fma2(a01, W0.x, acc[0][1][0]);
                acc[0][1][1] = fma2(a01, W1.x, acc[0][1][1]);
                acc[0][1][2] = fma2(a01, W2.x, acc[0][1][2]);
                acc[0][1][3] = fma2(a01, W3.x, acc[0][1][3]);
                acc[1][0][0] = fma2(a10, W0.x, acc[1][0][0]);
                acc[1][0][1] = fma2(a10, W1.x, acc[1][0][1]);
                acc[1][0][2] = fma2(a10, W2.x, acc[1][0][2]);
                acc[1][0][3] = fma2(a10, W3.x, acc[1][0][3]);
                acc[1][1][0] = fma2(a11, W0.x, acc[1][1][0]);
                acc[1][1][1] = fma2(a11, W1.x, acc[1][1][1]);
                acc[1][1][2] = fma2(a11, W2.x, acc[1][1][2]);
                acc[1][1][3] = fma2(a11, W3.x, acc[1][1][3]);
            }
            // c-pair (c+2, c+3)
            {
                u64 a00 = FABS2(add2(S0.y, P0.y));
                u64 a01 = FABS2(add2(S1.y, P0.y));
                u64 a10 = FABS2(add2(S0.y, P1.y));
                u64 a11 = FABS2(add2(S1.y, P1.y));
                acc[0][0][0] = fma2(a00, W0.y, acc[0][0][0]);
                acc[0][0][1] = fma2(a00, W1.y, acc[0][0][1]);
                acc[0][0][2] = fma2(a00, W2.y, acc[0][0][2]);
                acc[0][0][3] = fma2(a00, W3.y, acc[0][0][3]);
                acc[0][1][0] = fma2(a01, W0.y, acc[0][1][0]);
                acc[0][1][1] = fma2(a01, W1.y, acc[0][1][1]);
                acc[0][1][2] = fma2(a01, W2.y, acc[0][1][2]);
                acc[0][1][3] = fma2(a01, W3.y, acc[0][1][3]);
                acc[1][0][0] = fma2(a10, W0.y, acc[1][0][0]);
                acc[1][0][1] = fma2(a10, W1.y, acc[1][0][1]);
                acc[1][0][2] = fma2(a10, W2.y, acc[1][0][2]);
                acc[1][0][3] = fma2(a10, W3.y, acc[1][0][3]);
                acc[1][1][0] = fma2(a11, W0.y, acc[1][1][0]);
                acc[1][1][1] = fma2(a11, W1.y, acc[1][1][1]);
                acc[1][1][2] = fma2(a11, W2.y, acc[1][1][2]);
                acc[1][1][3] = fma2(a11, W3.y, acc[1][1][3]);
            }
        }
        __syncthreads();
    }

    // Epilogue: z = relu(sum + bias), e = expf(z); write e; partial sums
    const float4 btv = *(const float4*)b_t;
    const float bt[4] = {btv.x, btv.y, btv.z, btv.w};

    float4 ps[2];
    ps[0] = make_float4(0.f, 0.f, 0.f, 0.f);
    ps[1] = make_float4(0.f, 0.f, 0.f, 0.f);

    #pragma unroll
    for (int p = 0; p < 2; p++) {
        int i = i0 + 2 * ty + p;
        #pragma unroll
        for (int q = 0; q < 2; q++) {
            int j = j0 + 2 * tx + q;
            float e[4];
            #pragma unroll
            for (int h = 0; h < 4; h++) {
                float2 f = unpack2(acc[p][q][h]);
                float z = fmaxf(f.x + f.y + bt[h], 0.0f);
                e[h] = __expf(z);
            }
            float4 ev = make_float4(e[0], e[1], e[2], e[3]);
            *(float4*)&attn[(((size_t)(b * T + i)) * T + j) * HEADS] = ev;
            ps[p].x += ev.x; ps[p].y += ev.y; ps[p].z += ev.z; ps[p].w += ev.w;
        }
    }

    // reduce partial sums across tx (16 lanes of the half-warp)
    #pragma unroll
    for (int p = 0; p < 2; p++) {
        #pragma unroll
        for (int m = 8; m >= 1; m >>= 1) {
            ps[p].x += __shfl_xor_sync(0xffffffffu, ps[p].x, m);
            ps[p].y += __shfl_xor_sync(0xffffffffu, ps[p].y, m);
            ps[p].z += __shfl_xor_sync(0xffffffffu, ps[p].z, m);
            ps[p].w += __shfl_xor_sync(0xffffffffu, ps[p].w, m);
        }
    }
    if (tx == 0) {
        #pragma unroll
        for (int p = 0; p < 2; p++) {
            int i = i0 + 2 * ty + p;
            *(float4*)&part[((size_t)(b * T + i) * NJT + jt) * HEADS] = ps[p];
        }
    }
}

// ---------------------------------------------------------------------------
// Kernel 3b: normalize + mask.  One block per (b,i); 256 threads x 2 j each.
// ---------------------------------------------------------------------------
__global__ void normalize_kernel(const float* __restrict__ part,
                                 const int* __restrict__ mask,
                                 float* __restrict__ attn) {
    int bi = blockIdx.x;               // b*T + i
    int tid = threadIdx.x;

    float4 rs = make_float4(0.f, 0.f, 0.f, 0.f);
    #pragma unroll
    for (int jt = 0; jt < NJT; jt++) {
        float4 v = *(const float4*)&part[((size_t)bi * NJT + jt) * HEADS];
        rs.x += v.x; rs.y += v.y; rs.z += v.z; rs.w += v.w;
    }
    float4 inv = make_float4(1.f / rs.x, 1.f / rs.y, 1.f / rs.z, 1.f / rs.w);

    int mi = mask[bi];
    int jrow = bi & ~(T - 1);          // b*T
    #pragma unroll
    for (int r = 0; r < 2; r++) {
        int j = tid + r * 256;
        size_t idx = ((size_t)bi * T + j) * HEADS;
        float4 v = *(const float4*)&attn[idx];
        int mj = mask[jrow + j];
        float kill = (mi && mj) ? 0.0f : 1.0f;
        v.x *= inv.x * kill;
        v.y *= inv.y * kill;
        v.z *= inv.z * kill;
        v.w *= inv.w * kill;
        *(float4*)&attn[idx] = v;
    }
}

// ---------------------------------------------------------------------------
extern "C" void kernel_launch(void* const* d_in, const int* in_sizes, int n_in,
                              void* d_out, int out_size) {
    const float* x      = (const float*)d_in[0];
    const float* W_subj = (const float*)d_in[1];
    const float* b_subj = (const float*)d_in[2];
    const float* W_obj  = (const float*)d_in[3];
    const float* b_obj  = (const float*)d_in[4];
    const float* W_t    = (const float*)d_in[5];
    const float* b_t    = (const float*)d_in[6];
    const int*   mask   = (const int*)d_in[7];

    float* out   = (float*)d_out;
    float* xnew  = out;                          // (B,T,2C)
    float* attn  = out + (size_t)B * T * C2;     // (B,T,T,HEADS)

    float *subj, *obj, *part;
    cudaGetSymbolAddress((void**)&subj, g_subj);
    cudaGetSymbolAddress((void**)&obj, g_obj);
    cudaGetSymbolAddress((void**)&part, g_part);

    pool_concat_kernel<<<(B * T * C2 + 255) / 256, 256>>>(x, xnew);

    dim3 gg(C / 64, (B * T) / 64, 2);   // (4, 32, 2)
    gemm_kernel<<<gg, 256>>>(xnew, W_subj, b_subj, W_obj, b_obj, subj, obj);

    dim3 ga(NJT, T / TI, B);            // (16, 16, 4) = 1024 blocks
    rep_exp_kernel<<<ga, 256>>>(subj, obj, W_t, b_t, attn, part);

    normalize_kernel<<<B * T, 256>>>(part, mask, attn);
}

// round 4
// speedup vs baseline: 2.0078x; 1.0169x over previous
#include <cuda_runtime.h>
#include <cuda_bf16.h>
#include <math.h>

// Problem constants
#define B 4
#define T 512
#define C 256
#define C2 512
#define HEADS 4
#define MAXOFF 2

#define TI 32          // i-tile per block
#define TJ 32          // j-tile per block
#define NJT (T / TJ)   // 16 j-tiles
#define CK 128         // c chunk

typedef unsigned long long u64;

// Scratch (allocation-free: device globals)
__device__ float g_subj[B * T * C];
__device__ float g_obj[B * T * C];
__device__ float g_part[B * T * NJT * HEADS];   // partial exp-sums per j-tile
__device__ float g_inv[B * T * HEADS];          // 1 / softmax denominator

// packed f32x2 helpers
static __device__ __forceinline__ u64 add2(u64 a, u64 b) {
    u64 r; asm("add.rn.f32x2 %0, %1, %2;" : "=l"(r) : "l"(a), "l"(b)); return r;
}
static __device__ __forceinline__ u64 fma2(u64 a, u64 b, u64 c) {
    u64 r; asm("fma.rn.f32x2 %0, %1, %2, %3;" : "=l"(r) : "l"(a), "l"(b), "l"(c)); return r;
}
static __device__ __forceinline__ float2 unpack2(u64 v) {
    float2 r; asm("mov.b64 {%0, %1}, %2;" : "=f"(r.x), "=f"(r.y) : "l"(v)); return r;
}
#define FABS2(v) ((v) & 0x7fffffff7fffffffULL)

// ---------------------------------------------------------------------------
// Kernel 1: max-pool along channel (window 5, pad 2) + concat -> x_new
// ---------------------------------------------------------------------------
__global__ void pool_concat_kernel(const float* __restrict__ x,
                                   float* __restrict__ xnew) {
    int idx = blockIdx.x * 256 + threadIdx.x;
    if (idx >= B * T * C2) return;
    int cc = idx & (C2 - 1);
    int bt = idx >> 9;
    const float* xr = x + bt * C;
    float v;
    if (cc < C) {
        int lo = cc - MAXOFF; if (lo < 0) lo = 0;
        int hi = cc + MAXOFF; if (hi > C - 1) hi = C - 1;
        v = -INFINITY;
        #pragma unroll 5
        for (int c = lo; c <= hi; c++) v = fmaxf(v, xr[c]);
    } else {
        v = xr[cc - C];
    }
    xnew[idx] = v;
}

// ---------------------------------------------------------------------------
// Kernel 2: both projection GEMMs in one launch (blockIdx.z selects W/bias/out)
// ---------------------------------------------------------------------------
__global__ void gemm_kernel(const float* __restrict__ A,
                            const float* __restrict__ W0,
                            const float* __restrict__ b0,
                            const float* __restrict__ W1,
                            const float* __restrict__ b1,
                            float* __restrict__ out0,
                            float* __restrict__ out1) {
    const int N = C;
    const int K = C2;

    const float* W    = blockIdx.z ? W1 : W0;
    const float* bias = blockIdx.z ? b1 : b0;
    float* out        = blockIdx.z ? out1 : out0;

    __shared__ float As[16][68];
    __shared__ float Ws[16][64];

    int tid = threadIdx.x;
    int tx = tid & 15;
    int ty = tid >> 4;
    int bm = blockIdx.y * 64;
    int bn = blockIdx.x * 64;

    float acc[4][4];
    #pragma unroll
    for (int i = 0; i < 4; i++)
        #pragma unroll
        for (int j = 0; j < 4; j++) acc[i][j] = 0.0f;

    for (int k0 = 0; k0 < K; k0 += 16) {
        #pragma unroll
        for (int l = 0; l < 4; l++) {
            int idx = tid + l * 256;
            int m = idx >> 4, ka = idx & 15;
            As[ka][m] = A[(bm + m) * K + k0 + ka];
            int n2 = idx & 63, kw = idx >> 6;
            Ws[kw][n2] = W[(k0 + kw) * N + bn + n2];
        }
        __syncthreads();
        #pragma unroll
        for (int k = 0; k < 16; k++) {
            float a[4], w[4];
            #pragma unroll
            for (int i = 0; i < 4; i++) a[i] = As[k][ty * 4 + i];
            float4 wv = *(const float4*)&Ws[k][tx * 4];
            w[0] = wv.x; w[1] = wv.y; w[2] = wv.z; w[3] = wv.w;
            #pragma unroll
            for (int i = 0; i < 4; i++)
                #pragma unroll
                for (int j = 0; j < 4; j++)
                    acc[i][j] += a[i] * w[j];
        }
        __syncthreads();
    }

    float4 bv = *(const float4*)&bias[bn + tx * 4];
    #pragma unroll
    for (int i = 0; i < 4; i++) {
        float4 o;
        o.x = acc[i][0] + bv.x;
        o.y = acc[i][1] + bv.y;
        o.z = acc[i][2] + bv.z;
        o.w = acc[i][3] + bv.w;
        *(float4*)&out[(bm + ty * 4 + i) * N + bn + tx * 4] = o;
    }
}

// ---------------------------------------------------------------------------
// Kernel 3a: e = exp(relu(rep)) for a 32x32 (i,j) tile.
// 128 threads = 8 tx (j, stride-8 quads) x 16 ty (i pairs, stride-16).
// Microtile 2i x 4j, c packed in f32x2 pairs. Swizzled conflict-free smem.
// ---------------------------------------------------------------------------
__global__ void __launch_bounds__(128)
rep_exp_kernel(const float* __restrict__ subj,
               const float* __restrict__ obj,
               const float* __restrict__ W_t,
               const float* __restrict__ b_t,
               float* __restrict__ attn,
               float* __restrict__ part) {
    __shared__ float s_sh[TJ * CK];     // [jrow][c], swizzled
    __shared__ float o_sh[TI * CK];     // [irow][c], swizzled, holds -obj
    __shared__ float w_sh[HEADS * C];   // [h][c]

    const int tid = threadIdx.x;
    const int tx = tid & 7;            // j groups
    const int ty = tid >> 3;           // 0..15, i pairs
    const int jt = blockIdx.x;
    const int j0 = jt * TJ;
    const int i0 = blockIdx.y * TI;
    const int b  = blockIdx.z;

    // Load W_t transposed: w_sh[h][c] = W_t[c*4+h]
    #pragma unroll
    for (int c = tid; c < C; c += 128) {
        float4 wv = *(const float4*)&W_t[c * 4];
        w_sh[0 * C + c] = wv.x;
        w_sh[1 * C + c] = wv.y;
        w_sh[2 * C + c] = wv.z;
        w_sh[3 * C + c] = wv.w;
    }

    u64 acc[2][4][4];
    #pragma unroll
    for (int p = 0; p < 2; p++)
        #pragma unroll
        for (int q = 0; q < 4; q++)
            #pragma unroll
            for (int h = 0; h < 4; h++) acc[p][q][h] = 0ULL;

    const int swi = ty & 7;
    const float* sp[4];
    #pragma unroll
    for (int q = 0; q < 4; q++) sp[q] = s_sh + (tx + 8 * q) * CK;
    const float* op0 = o_sh + ty * CK;
    const float* op1 = o_sh + (ty + 16) * CK;

    for (int ck = 0; ck < C / CK; ck++) {
        const int cbase = ck * CK;
        // load s/o chunk (32 rows x 128 c), coalesced gmem, swizzled smem
        #pragma unroll
        for (int l = 0; l < 8; l++) {
            int t = tid + l * 128;
            int row = t >> 5;          // 0..31
            int ccg = t & 31;          // 16B group within chunk
            int phys = (ccg ^ (row & 7)) << 2;
            float4 sv = *(const float4*)&subj[(b * T + j0 + row) * C + cbase + ccg * 4];
            *(float4*)&s_sh[row * CK + phys] = sv;
            float4 ov = *(const float4*)&obj[(b * T + i0 + row) * C + cbase + ccg * 4];
            ov.x = -ov.x; ov.y = -ov.y; ov.z = -ov.z; ov.w = -ov.w;
            *(float4*)&o_sh[row * CK + phys] = ov;
        }
        __syncthreads();

        const float* wp0 = w_sh + 0 * C + cbase;
        const float* wp1 = w_sh + 1 * C + cbase;
        const float* wp2 = w_sh + 2 * C + cbase;
        const float* wp3 = w_sh + 3 * C + cbase;

        #pragma unroll 4
        for (int g = 0; g < CK / 4; g++) {
            int gs = (g ^ tx) << 2;
            int gi = (g ^ swi) << 2;
            ulonglong2 S0 = *(const ulonglong2*)(sp[0] + gs);
            ulonglong2 S1 = *(const ulonglong2*)(sp[1] + gs);
            ulonglong2 S2 = *(const ulonglong2*)(sp[2] + gs);
            ulonglong2 S3 = *(const ulonglong2*)(sp[3] + gs);
            ulonglong2 P0 = *(const ulonglong2*)(op0 + gi);
            ulonglong2 P1 = *(const ulonglong2*)(op1 + gi);
            ulonglong2 W0 = *(const ulonglong2*)(wp0 + g * 4);
            ulonglong2 W1 = *(const ulonglong2*)(wp1 + g * 4);
            ulonglong2 W2 = *(const ulonglong2*)(wp2 + g * 4);
            ulonglong2 W3 = *(const ulonglong2*)(wp3 + g * 4);

            // ---- c-pair (c, c+1) ----
            {
                u64 a;
                a = FABS2(add2(S0.x, P0.x));
                acc[0][0][0] = fma2(a, W0.x, acc[0][0][0]);
                acc[0][0][1] = fma2(a, W1.x, acc[0][0][1]);
                acc[0][0][2] = fma2(a, W2.x, acc[0][0][2]);
                acc[0][0][3] = fma2(a, W3.x, acc[0][0][3]);
                a = FABS2(add2(S1.x, P0.x));
                acc[0][1][0] = fma2(a, W0.x, acc[0][1][0]);
                acc[0][1][1] = fma2(a, W1.x, acc[0][1][1]);
                acc[0][1][2] = fma2(a, W2.x, acc[0][1][2]);
                acc[0][1][3] = fma2(a, W3.x, acc[0][1][3]);
                a = FABS2(add2(S2.x, P0.x));
                acc[0][2][0] = fma2(a, W0.x, acc[0][2][0]);
                acc[0][2][1] = fma2(a, W1.x, acc[0][2][1]);
                acc[0][2][2] = fma2(a, W2.x, acc[0][2][2]);
                acc[0][2][3] = fma2(a, W3.x, acc[0][2][3]);
                a = FABS2(add2(S3.x, P0.x));
                acc[0][3][0] = fma2(a, W0.x, acc[0][3][0]);
                acc[0][3][1] = fma2(a, W1.x, acc[0][3][1]);
                acc[0][3][2] = fma2(a, W2.x, acc[0][3][2]);
                acc[0][3][3] = fma2(a, W3.x, acc[0][3][3]);
                a = FABS2(add2(S0.x, P1.x));
                acc[1][0][0] = fma2(a, W0.x, acc[1][0][0]);
                acc[1][0][1] = fma2(a, W1.x, acc[1][0][1]);
                acc[1][0][2] = fma2(a, W2.x, acc[1][0][2]);
                acc[1][0][3] = fma2(a, W3.x, acc[1][0][3]);
                a = FABS2(add2(S1.x, P1.x));
                acc[1][1][0] = fma2(a, W0.x, acc[1][1][0]);
                acc[1][1][1] = fma2(a, W1.x, acc[1][1][1]);
                acc[1][1][2] = fma2(a, W2.x, acc[1][1][2]);
                acc[1][1][3] = fma2(a, W3.x, acc[1][1][3]);
                a = FABS2(add2(S2.x, P1.x));
                acc[1][2][0] = fma2(a, W0.x, acc[1][2][0]);
                acc[1][2][1] = fma2(a, W1.x, acc[1][2][1]);
                acc[1][2][2] = fma2(a, W2.x, acc[1][2][2]);
                acc[1][2][3] = fma2(a, W3.x, acc[1][2][3]);
                a = FABS2(add2(S3.x, P1.x));
                acc[1][3][0] = fma2(a, W0.x, acc[1][3][0]);
                acc[1][3][1] = fma2(a, W1.x, acc[1][3][1]);
                acc[1][3][2] = fma2(a, W2.x, acc[1][3][2]);
                acc[1][3][3] = fma2(a, W3.x, acc[1][3][3]);
            }
            // ---- c-pair (c+2, c+3) ----
            {
                u64 a;
                a = FABS2(add2(S0.y, P0.y));
                acc[0][0][0] = fma2(a, W0.y, acc[0][0][0]);
                acc[0][0][1] = fma2(a, W1.y, acc[0][0][1]);
                acc[0][0][2] = fma2(a, W2.y, acc[0][0][2]);
                acc[0][0][3] = fma2(a, W3.y, acc[0][0][3]);
                a = FABS2(add2(S1.y, P0.y));
                acc[0][1][0] = fma2(a, W0.y, acc[0][1][0]);
                acc[0][1][1] = fma2(a, W1.y, acc[0][1][1]);
                acc[0][1][2] = fma2(a, W2.y, acc[0][1][2]);
                acc[0][1][3] = fma2(a, W3.y, acc[0][1][3]);
                a = FABS2(add2(S2.y, P0.y));
                acc[0][2][0] = fma2(a, W0.y, acc[0][2][0]);
                acc[0][2][1] = fma2(a, W1.y, acc[0][2][1]);
                acc[0][2][2] = fma2(a, W2.y, acc[0][2][2]);
                acc[0][2][3] = fma2(a, W3.y, acc[0][2][3]);
                a = FABS2(add2(S3.y, P0.y));
                acc[0][3][0] = fma2(a, W0.y, acc[0][3][0]);
                acc[0][3][1] = fma2(a, W1.y, acc[0][3][1]);
                acc[0][3][2] = fma2(a, W2.y, acc[0][3][2]);
                acc[0][3][3] = fma2(a, W3.y, acc[0][3][3]);
                a = FABS2(add2(S0.y, P1.y));
                acc[1][0][0] = fma2(a, W0.y, acc[1][0][0]);
                acc[1][0][1] = fma2(a, W1.y, acc[1][0][1]);
                acc[1][0][2] = fma2(a, W2.y, acc[1][0][2]);
                acc[1][0][3] = fma2(a, W3.y, acc[1][0][3]);
                a = FABS2(add2(S1.y, P1.y));
                acc[1][1][0] = fma2(a, W0.y, acc[1][1][0]);
                acc[1][1][1] = fma2(a, W1.y, acc[1][1][1]);
                acc[1][1][2] = fma2(a, W2.y, acc[1][1][2]);
                acc[1][1][3] = fma2(a, W3.y, acc[1][1][3]);
                a = FABS2(add2(S2.y, P1.y));
                acc[1][2][0] = fma2(a, W0.y, acc[1][2][0]);
                acc[1][2][1] = fma2(a, W1.y, acc[1][2][1]);
                acc[1][2][2] = fma2(a, W2.y, acc[1][2][2]);
                acc[1][2][3] = fma2(a, W3.y, acc[1][2][3]);
                a = FABS2(add2(S3.y, P1.y));
                acc[1][3][0] = fma2(a, W0.y, acc[1][3][0]);
                acc[1][3][1] = fma2(a, W1.y, acc[1][3][1]);
                acc[1][3][2] = fma2(a, W2.y, acc[1][3][2]);
                acc[1][3][3] = fma2(a, W3.y, acc[1][3][3]);
            }
        }
        __syncthreads();
    }

    // Epilogue: z = relu(sum + bias), e = exp(z); write e; per-i partial sums
    const float4 btv = *(const float4*)b_t;
    const float bt[4] = {btv.x, btv.y, btv.z, btv.w};

    #pragma unroll
    for (int p = 0; p < 2; p++) {
        int i = i0 + ty + 16 * p;
        float4 ps = make_float4(0.f, 0.f, 0.f, 0.f);
        #pragma unroll
        for (int q = 0; q < 4; q++) {
            int j = j0 + tx + 8 * q;
            float e[4];
            #pragma unroll
            for (int h = 0; h < 4; h++) {
                float2 f = unpack2(acc[p][q][h]);
                float z = fmaxf(f.x + f.y + bt[h], 0.0f);
                e[h] = __expf(z);
            }
            float4 ev = make_float4(e[0], e[1], e[2], e[3]);
            *(float4*)&attn[(((size_t)(b * T + i)) * T + j) * HEADS] = ev;
            ps.x += ev.x; ps.y += ev.y; ps.z += ev.z; ps.w += ev.w;
        }
        // reduce across tx (8 lanes)
        #pragma unroll
        for (int m = 4; m >= 1; m >>= 1) {
            ps.x += __shfl_xor_sync(0xffffffffu, ps.x, m);
            ps.y += __shfl_xor_sync(0xffffffffu, ps.y, m);
            ps.z += __shfl_xor_sync(0xffffffffu, ps.z, m);
            ps.w += __shfl_xor_sync(0xffffffffu, ps.w, m);
        }
        if (tx == 0)
            *(float4*)&part[((size_t)(b * T + i) * NJT + jt) * HEADS] = ps;
    }
}

// ---------------------------------------------------------------------------
// Kernel 3b: per-(i,h) softmax denominator inverse.
// ---------------------------------------------------------------------------
__global__ void suminv_kernel(const float* __restrict__ part,
                              float* __restrict__ inv) {
    int idx = blockIdx.x * 256 + threadIdx.x;   // B*T*HEADS = 8192
    int bi = idx >> 2, h = idx & 3;
    float s = 0.f;
    #pragma unroll
    for (int jt = 0; jt < NJT; jt++)
        s += part[((size_t)bi * NJT + jt) * HEADS + h];
    inv[idx] = 1.0f / s;
}

// ---------------------------------------------------------------------------
// Kernel 3c: normalize + mask. One float4 per thread.
// ---------------------------------------------------------------------------
__global__ void normalize_kernel(const float* __restrict__ inv,
                                 const int* __restrict__ mask,
                                 float* __restrict__ attn) {
    int f = blockIdx.x * 256 + threadIdx.x;     // B*T*T = 1048576
    int j = f & (T - 1);
    int bi = f >> 9;
    int b = bi >> 9;

    float4 v = *(const float4*)&attn[(size_t)f * HEADS];
    float4 iv = *(const float4*)&inv[bi * HEADS];
    int mi = mask[bi];
    int mj = mask[b * T + j];
    float kill = (mi && mj) ? 0.0f : 1.0f;
    v.x *= iv.x * kill;
    v.y *= iv.y * kill;
    v.z *= iv.z * kill;
    v.w *= iv.w * kill;
    *(float4*)&attn[(size_t)f * HEADS] = v;
}

// ---------------------------------------------------------------------------
extern "C" void kernel_launch(void* const* d_in, const int* in_sizes, int n_in,
                              void* d_out, int out_size) {
    const float* x      = (const float*)d_in[0];
    const float* W_subj = (const float*)d_in[1];
    const float* b_subj = (const float*)d_in[2];
    const float* W_obj  = (const float*)d_in[3];
    const float* b_obj  = (const float*)d_in[4];
    const float* W_t    = (const float*)d_in[5];
    const float* b_t    = (const float*)d_in[6];
    const int*   mask   = (const int*)d_in[7];

    float* out   = (float*)d_out;
    float* xnew  = out;                          // (B,T,2C)
    float* attn  = out + (size_t)B * T * C2;     // (B,T,T,HEADS)

    float *subj, *obj, *part, *inv;
    cudaGetSymbolAddress((void**)&subj, g_subj);
    cudaGetSymbolAddress((void**)&obj, g_obj);
    cudaGetSymbolAddress((void**)&part, g_part);
    cudaGetSymbolAddress((void**)&inv, g_inv);

    pool_concat_kernel<<<(B * T * C2 + 255) / 256, 256>>>(x, xnew);

    dim3 gg(C / 64, (B * T) / 64, 2);   // (4, 32, 2)
    gemm_kernel<<<gg, 256>>>(xnew, W_subj, b_subj, W_obj, b_obj, subj, obj);

    dim3 ga(NJT, T / TI, B);            // (16, 16, 4) = 1024 blocks
    rep_exp_kernel<<<ga, 128>>>(subj, obj, W_t, b_t, attn, part);

    suminv_kernel<<<(B * T * HEADS) / 256, 256>>>(part, inv);

    normalize_kernel<<<(B * T * T) / 256, 256>>>(inv, mask, attn);
}